// round 17
// baseline (speedup 1.0000x reference)
#include <cuda_runtime.h>

// Salt & pepper noise apply: out = u < 0.01 ? 0 : (u < 0.02 ? 1 : x)
// HBM-bound stream (2 reads + 1 write, 604 MB). Optimizations vs R15:
//  - 2x float4 per thread (4 outstanding LDG.128 -> higher MLP)
//  - __ldcs / __stcs streaming cache hints (zero-reuse working set >> L2)

static __device__ __forceinline__ float sp(float x, float u) {
    float v = (u < 0.02f) ? 1.0f : x;
    return (u < 0.01f) ? 0.0f : v;
}

static __device__ __forceinline__ float4 sp4(float4 x, float4 u) {
    float4 r;
    r.x = sp(x.x, u.x);
    r.y = sp(x.y, u.y);
    r.z = sp(x.z, u.z);
    r.w = sp(x.w, u.w);
    return r;
}

__global__ void __launch_bounds__(256)
salt_pepper_kernel(const float4* __restrict__ img,
                   const float4* __restrict__ uni,
                   float4* __restrict__ out,
                   int n4) {
    int i0 = blockIdx.x * (blockDim.x * 2) + threadIdx.x;
    int i1 = i0 + blockDim.x;
    if (i1 < n4) {
        // Front-batch all 4 loads for max MLP before any dependent use.
        float4 x0 = __ldcs(&img[i0]);
        float4 u0 = __ldcs(&uni[i0]);
        float4 x1 = __ldcs(&img[i1]);
        float4 u1 = __ldcs(&uni[i1]);
        __stcs(&out[i0], sp4(x0, u0));
        __stcs(&out[i1], sp4(x1, u1));
    } else if (i0 < n4) {
        float4 x0 = __ldcs(&img[i0]);
        float4 u0 = __ldcs(&uni[i0]);
        __stcs(&out[i0], sp4(x0, u0));
    }
}

// Scalar tail fallback in case element count isn't divisible by 4
__global__ void salt_pepper_tail(const float* __restrict__ img,
                                 const float* __restrict__ uni,
                                 float* __restrict__ out,
                                 int start, int n) {
    int i = start + blockIdx.x * blockDim.x + threadIdx.x;
    if (i < n) {
        out[i] = sp(img[i], uni[i]);
    }
}

extern "C" void kernel_launch(void* const* d_in, const int* in_sizes, int n_in,
                              void* d_out, int out_size) {
    const float* img = (const float*)d_in[0];
    const float* uni = (const float*)d_in[1];
    float* out = (float*)d_out;
    int n = in_sizes[0];

    int n4 = n / 4;
    if (n4 > 0) {
        const int threads = 256;
        const int per_block = threads * 2;  // 2 float4 per thread
        int blocks = (n4 + per_block - 1) / per_block;
        salt_pepper_kernel<<<blocks, threads>>>(
            (const float4*)img, (const float4*)uni, (float4*)out, n4);
    }
    int rem = n - n4 * 4;
    if (rem > 0) {
        salt_pepper_tail<<<1, 256>>>(img, uni, out, n4 * 4, n);
    }
}